// round 16
// baseline (speedup 1.0000x reference)
#include <cuda_runtime.h>
#include <math.h>

#define BB 4
#define NSEQ 8192
#define DD 512
#define HH 2
#define DH 64
#define INNER 128
#define MM 256
#define LLM 32
#define BH (BB*HH)
#define TOK (BB*NSEQ)
#define KERN 33
#define NSP 8

typedef unsigned u32;

__device__ u32   g_xnh[(size_t)TOK*256];
__device__ u32   g_wqkvh[256*384];              // w_qkv bf16x2 [k/2][n]
__device__ u32   g_wouth[64*512];               // w_out bf16x2 [k/2][n]
__device__ u32   g_qh[(size_t)BH*NSEQ*32];
__device__ u32   g_kh[(size_t)BH*NSEQ*32];
__device__ u32   g_vh[(size_t)BH*NSEQ*32];
__device__ float g_ql[BH*MM*DH];
__device__ float g_kl[BH*MM*DH];
__device__ float g_a2[BH*MM*MM];
__device__ float g_xz[BH*MM*MM];
__device__ float g_t1[BH*MM*MM];
__device__ float g_t2[BH*MM*MM];
__device__ float g_za[BH*MM*MM];
__device__ float g_zb[BH*MM*MM];
__device__ float g_a3v[BH*MM*DH];
__device__ float g_w2[BH*MM*DH];
__device__ u32   g_out1h[(size_t)BH*NSEQ*32];
__device__ float g_part[BH*NSP*MM*DH];
__device__ float g_m[BH*NSP*MM];
__device__ float g_l[BH*NSP*MM];
__device__ unsigned g_max0, g_max1;

// ---- helpers ----
__device__ __forceinline__ unsigned f2tf(float f) {
    unsigned r; asm("cvt.rna.tf32.f32 %0, %1;" : "=r"(r) : "f"(f)); return r;
}
__device__ __forceinline__ void mma8(float* c, const unsigned* a, const unsigned* b) {
    asm volatile("mma.sync.aligned.m16n8k8.row.col.f32.tf32.tf32.f32 "
        "{%0,%1,%2,%3}, {%4,%5,%6,%7}, {%8,%9}, {%0,%1,%2,%3};"
        : "+f"(c[0]), "+f"(c[1]), "+f"(c[2]), "+f"(c[3])
        : "r"(a[0]), "r"(a[1]), "r"(a[2]), "r"(a[3]), "r"(b[0]), "r"(b[1]));
}
__device__ __forceinline__ u32 pk2(float lo, float hi) {
    u32 r; asm("cvt.rn.bf16x2.f32 %0, %2, %1;" : "=r"(r) : "f"(lo), "f"(hi)); return r;
}
__device__ __forceinline__ void mmab(float* c, const u32* a, const u32* b) {
    asm volatile("mma.sync.aligned.m16n8k16.row.col.f32.bf16.bf16.f32 "
        "{%0,%1,%2,%3}, {%4,%5,%6,%7}, {%8,%9}, {%0,%1,%2,%3};"
        : "+f"(c[0]), "+f"(c[1]), "+f"(c[2]), "+f"(c[3])
        : "r"(a[0]), "r"(a[1]), "r"(a[2]), "r"(a[3]), "r"(b[0]), "r"(b[1]));
}
__device__ __forceinline__ uint4 pkA(float4 v1, float4 v2) {
    return make_uint4(pk2(v1.x,v1.y), pk2(v1.z,v1.w), pk2(v2.x,v2.y), pk2(v2.z,v2.w));
}
__device__ __forceinline__ uint4 pkB(float4 r1, float4 r2) {
    return make_uint4(pk2(r1.x,r2.x), pk2(r1.y,r2.y), pk2(r1.z,r2.z), pk2(r1.w,r2.w));
}
__device__ __forceinline__ void ldsm4(u32* r, u32 addr) {
    asm volatile("ldmatrix.sync.aligned.m8n8.x4.shared.b16 {%0,%1,%2,%3}, [%4];"
        : "=r"(r[0]), "=r"(r[1]), "=r"(r[2]), "=r"(r[3]) : "r"(addr));
}
__device__ __forceinline__ u32 shaddr(const void* p) {
    return (u32)__cvta_generic_to_shared(p);
}
__device__ __forceinline__ float blo(u32 w) { return __uint_as_float(w << 16); }
__device__ __forceinline__ float bhi(u32 w) { return __uint_as_float(w & 0xFFFF0000u); }

__global__ void init_kernel() { g_max0 = 0u; g_max1 = 0u; }

__global__ void prepack_kernel(const float* __restrict__ wqkv, const float* __restrict__ wout) {
    int idx = blockIdx.x * 256 + threadIdx.x;
    if (idx < 256 * 384) {
        int kp = idx / 384, n = idx % 384;
        g_wqkvh[idx] = pk2(wqkv[(size_t)(2*kp) * 384 + n], wqkv[(size_t)(2*kp+1) * 384 + n]);
    } else {
        int j = idx - 256 * 384;
        int kp = j / 512, n = j % 512;
        g_wouth[j] = pk2(wout[(size_t)(2*kp) * 512 + n], wout[(size_t)(2*kp+1) * 512 + n]);
    }
}

__global__ __launch_bounds__(128) void ln_kernel(const float* __restrict__ x,
                                                 const float* __restrict__ gamma,
                                                 const float* __restrict__ beta) {
    int t = blockIdx.x, tid = threadIdx.x;
    const float4* xr = (const float4*)(x + (size_t)t * DD);
    float4 v = xr[tid];
    float s  = v.x + v.y + v.z + v.w;
    float sq = v.x*v.x + v.y*v.y + v.z*v.z + v.w*v.w;
    __shared__ float sb[8];
    #pragma unroll
    for (int o = 16; o; o >>= 1) {
        s  += __shfl_xor_sync(0xffffffffu, s, o);
        sq += __shfl_xor_sync(0xffffffffu, sq, o);
    }
    int w = tid >> 5, l = tid & 31;
    if (l == 0) { sb[w] = s; sb[4 + w] = sq; }
    __syncthreads();
    if (tid == 0) { sb[0] = sb[0]+sb[1]+sb[2]+sb[3]; sb[4] = sb[4]+sb[5]+sb[6]+sb[7]; }
    __syncthreads();
    float mu  = sb[0] * (1.f / DD);
    float var = sb[4] * (1.f / DD) - mu * mu;
    float rs  = rsqrtf(var + 1e-5f);
    float4 g4 = ((const float4*)gamma)[tid];
    float4 b4 = ((const float4*)beta)[tid];
    float4 o;
    o.x = (v.x - mu) * rs * g4.x + b4.x;
    o.y = (v.y - mu) * rs * g4.y + b4.y;
    o.z = (v.z - mu) * rs * g4.z + b4.z;
    o.w = (v.w - mu) * rs * g4.w + b4.w;
    uint2 pr = make_uint2(pk2(o.x, o.y), pk2(o.z, o.w));
    *(uint2*)&g_xnh[(size_t)t * 256 + tid * 2] = pr;
}

__global__ __launch_bounds__(256) void landmark_kernel() {
    __shared__ float4 rq[256], rk[256];
    int bh = blockIdx.x, m0 = blockIdx.y * 4;
    int tid = threadIdx.x;
    int l = tid >> 6, t2 = tid & 63;
    int rseg = t2 >> 4, dp = (t2 & 15) * 2;
    int m = m0 + l;
    size_t base = ((size_t)bh * NSEQ + m * LLM + rseg * 8) * 32 + dp;
    float4 sq = make_float4(0.f,0.f,0.f,0.f), sk = sq;
    #pragma unroll
    for (int i = 0; i < 8; i++) {
        uint2 a = *(const uint2*)&g_qh[base + (size_t)i * 32];
        uint2 b = *(const uint2*)&g_kh[base + (size_t)i * 32];
        sq.x += blo(a.x); sq.y += bhi(a.x); sq.z += blo(a.y); sq.w += bhi(a.y);
        sk.x += blo(b.x); sk.y += bhi(b.x); sk.z += blo(b.y); sk.w += bhi(b.y);
    }
    rq[tid] = sq; rk[tid] = sk;
    __syncthreads();
    if (rseg == 0) {
        #pragma unroll
        for (int u = 1; u < 4; u++) {
            float4 a = rq[tid + u * 16], b = rk[tid + u * 16];
            sq.x += a.x; sq.y += a.y; sq.z += a.z; sq.w += a.w;
            sk.x += b.x; sk.y += b.y; sk.z += b.z; sk.w += b.w;
        }
        const float inv = 1.f / LLM;
        sq.x *= inv; sq.y *= inv; sq.z *= inv; sq.w *= inv;
        sk.x *= inv; sk.y *= inv; sk.z *= inv; sk.w *= inv;
        *(float4*)&g_ql[(bh * MM + m) * DH + dp * 2] = sq;
        *(float4*)&g_kl[(bh * MM + m) * DH + dp * 2] = sk;
    }
}

__global__ __launch_bounds__(256) void sim2_kernel() {
    int bh = blockIdx.x >> 8, i = blockIdx.x & 255;
    int tid = threadIdx.x;
    __shared__ float qs[DH];
    __shared__ float red[8];
    if (tid < DH) qs[tid] = g_ql[(bh * MM + i) * DH + tid];
    __syncthreads();
    const float* kr = &g_kl[(bh * MM + tid) * DH];
    float s = 0.f;
    #pragma unroll
    for (int d = 0; d < DH; d += 4) {
        float4 kv = *(const float4*)&kr[d];
        s += qs[d]*kv.x + qs[d+1]*kv.y + qs[d+2]*kv.z + qs[d+3]*kv.w;
    }
    float m = s;
    #pragma unroll
    for (int o = 16; o; o >>= 1) m = fmaxf(m, __shfl_xor_sync(0xffffffffu, m, o));
    int w = tid >> 5, l = tid & 31;
    if (l == 0) red[w] = m;
    __syncthreads();
    if (w == 0) {
        float t = red[l & 7];
        #pragma unroll
        for (int o = 4; o; o >>= 1) t = fmaxf(t, __shfl_xor_sync(0xffffffffu, t, o));
        if (l == 0) red[0] = t;
    }
    __syncthreads();
    m = red[0];
    __syncthreads();
    float e = __expf(s - m);
    float su = e;
    #pragma unroll
    for (int o = 16; o; o >>= 1) su += __shfl_xor_sync(0xffffffffu, su, o);
    if (l == 0) red[w] = su;
    __syncthreads();
    if (w == 0) {
        float t = red[l & 7];
        #pragma unroll
        for (int o = 4; o; o >>= 1) t += __shfl_xor_sync(0xffffffffu, t, o);
        if (l == 0) red[0] = t;
    }
    __syncthreads();
    g_a2[((size_t)bh * MM + i) * MM + tid] = e / red[0];
}

__global__ __launch_bounds__(256) void absmax_kernel() {
    int bh = blockIdx.x, mode = blockIdx.y, tid = threadIdx.x;
    const float* A = &g_a2[(size_t)bh * MM * MM];
    float s = 0.f;
    if (mode == 0) { for (int j = 0; j < MM; j++) s += fabsf(A[tid * MM + j]); }
    else           { for (int i = 0; i < MM; i++) s += fabsf(A[i * MM + tid]); }
    float m = s;
    #pragma unroll
    for (int o = 16; o; o >>= 1) m = fmaxf(m, __shfl_xor_sync(0xffffffffu, m, o));
    __shared__ float red[8];
    int w = tid >> 5, l = tid & 31;
    if (l == 0) red[w] = m;
    __syncthreads();
    if (tid == 0) {
        float t = red[0];
        for (int u = 1; u < 8; u++) t = fmaxf(t, red[u]);
        atomicMax(mode == 0 ? &g_max0 : &g_max1, __float_as_uint(t));
    }
}

__global__ __launch_bounds__(256) void zinit_kernel() {
    int bh = blockIdx.x >> 8, i = blockIdx.x & 255, j = threadIdx.x;
    float inv = 1.f / (__uint_as_float(g_max0) * __uint_as_float(g_max1));
    g_za[((size_t)bh * MM + i) * MM + j] = g_a2[((size_t)bh * MM + j) * MM + i] * inv;
}

// ---------- bf16 packed GEMMs (R13-proven) ----------
__global__ __launch_bounds__(256) void qkv_mma() {
    __shared__ u32 SA[2][128*20];
    __shared__ u32 SB[2][16*136];
    int tid = threadIdx.x;
    int row0 = blockIdx.x * 128, col0 = blockIdx.y * 128;
    int lane = tid & 31, wid = tid >> 5;
    int g = lane >> 2, t = lane & 3;
    int wm = (wid & 1) * 64, wn = (wid >> 1) * 32;
    int mi = lane >> 3;
    int lrow = (lane & 7) + (mi & 1) * 8;
    int lcol = (mi >> 1) * 4;
    float acc[4][4][4];
    #pragma unroll
    for (int i = 0; i < 4; i++) for (int j = 0; j < 4; j++) for (int u = 0; u < 4; u++) acc[i][j][u] = 0.f;
    uint4 ua[2], ub[2];
    auto LOAD = [&](int kt) {
        int kp0 = kt >> 1;
        #pragma unroll
        for (int p = 0; p < 2; p++) {
            int idx = tid + p * 256; int m = idx >> 2, kg = idx & 3;
            ua[p] = *(const uint4*)&g_xnh[(size_t)(row0 + m) * 256 + kp0 + kg * 4];
        }
        #pragma unroll
        for (int p = 0; p < 2; p++) {
            int idx = tid + p * 256; int kp = idx >> 5, n4 = (idx & 31) * 4;
            ub[p] = *(const uint4*)&g_wqkvh[(size_t)(kp0 + kp) * 384 + col0 + n4];
        }
    };
    auto STS = [&](int buf) {
        #pragma unroll
        for (int p = 0; p < 2; p++) {
            int idx = tid + p * 256; int m = idx >> 2, kg = idx & 3;
            *(uint4*)&SA[buf][m * 20 + kg * 4] = ua[p];
        }
        #pragma unroll
        for (int p = 0; p < 2; p++) {
            int idx = tid + p * 256; int kp = idx >> 5, n4 = (idx & 31) * 4;
            *(uint4*)&SB[buf][kp * 136 + n4] = ub[p];
        }
    };
    auto COMP = [&](int buf) {
        u32 sa0 = shaddr(&SA[buf][(wm + lrow) * 20 + lcol]);
        #pragma unroll
        for (int s = 0; s < 2; s++) {
            int kp = 8 * s + t;
            u32 af[4][4], bf[4][2];
            #pragma unroll
            for (int i = 0; i < 4; i++)
                ldsm4(af[i], sa0 + ((16 * i * 20 + 8 * s) << 2));
            #pragma unroll
            for (int j = 0; j < 4; j++) {
                int n = wn + 8 * j + g;
                bf[j][0] = SB[buf][kp * 136 + n];
                bf[j][1] = SB[buf][(kp + 4) * 136 + n];
            }
            #pragma unroll
            for (int i = 0; i < 4; i++)
                #pragma unroll
                for (int j = 0; j < 4; j++) mmab(acc[i][j], af[i], bf[j]);
        }
    };
    LOAD(0); STS(0); __syncthreads();
    for (int it = 0; it < 16; it++) {
        if (it + 1 < 16) LOAD((it + 1) * 32);
        COMP(it & 1);
        if (it + 1 < 16) { STS((it + 1) & 1); __syncthreads(); }
    }
    auto STORE2 = [&](int tok, int c, float v0, float v1) {
        int bb = tok >> 13, n = tok & 8191;
        int which = c >> 7, hd = c & 127, h = hd >> 6, d = hd & 63;
        size_t dst = (((size_t)(bb * HH + h)) * NSEQ + n) * 32 + (d >> 1);
        if (which == 0)      g_qh[dst] = pk2(v0 * 0.125f, v1 * 0.125f);
        else if (which == 1) g_kh[dst] = pk2(v0, v1);
        else                 g_vh[dst] = pk2(v0, v1);
    };
    #pragma unroll
    for (int i = 0; i < 4; i++) {
        int row = row0 + wm + 16 * i + g;
        #pragma unroll
        for (int j = 0; j < 4; j++) {
            int col = col0 + wn + 8 * j + 2 * t;
            STORE2(row, col, acc[i][j][0], acc[i][j][1]);
            STORE2(row + 8, col, acc[i][j][2], acc[i][j][3]);
        }
    }
}

__global__ __launch_bounds__(256) void outgemm_mma(const float* __restrict__ x,
                                                   const float* __restrict__ bout,
                                                   float* __restrict__ out) {
    __shared__ u32 SA[2][128*20];
    __shared__ u32 SB[2][16*136];
    int tid = threadIdx.x;
    int row0 = blockIdx.x * 128, col0 = blockIdx.y * 128;
    int lane = tid & 31, wid = tid >> 5;
    int g = lane >> 2, t = lane & 3;
    int wm = (wid & 1) * 64, wn = (wid >> 1) * 32;
    int mi = lane >> 3;
    int lrow = (lane & 7) + (mi & 1) * 8;
    int lcol = (mi >> 1) * 4;
    float acc[4][4][4];
    #pragma unroll
    for (int i = 0; i < 4; i++) for (int j = 0; j < 4; j++) for (int u = 0; u < 4; u++) acc[i][j][u] = 0.f;
    uint4 ua[2], ub[2];
    auto LOAD = [&](int kt) {
        int kp0 = kt >> 1;
        #pragma unroll
        for (int p = 0; p < 2; p++) {
            int idx = tid + p * 256; int m = idx >> 2, kg = idx & 3;
            int tok = row0 + m; int bb = tok >> 13, n = tok & 8191;
            int kp = kp0 + kg * 4;
            int h = kp >> 5, dp = kp & 31;
            ua[p] = *(const uint4*)&g_out1h[(((size_t)(bb * HH + h)) * NSEQ + n) * 32 + dp];
        }
        #pragma unroll
        for (int p = 0; p < 2; p++) {
            int idx = tid + p * 256; int kp = idx >> 5, n4 = (idx & 31) * 4;
            ub[p] = *(const uint4*)&g_wouth[(size_t)(kp0 + kp) * 512 + col0 + n4];
        }
    };
    auto STS = [&](int buf) {
        #pragma unroll
        for (int p = 0; p < 2; p++) {
            int idx = tid + p * 256; int m = idx >> 2, kg = idx & 3;
            *(uint4*)&SA[buf][m * 20 + kg * 4] = ua[p];
        }
        #pragma unroll
        for (int p = 0; p < 2; p++) {
            int idx = tid + p * 256; int kp = idx >> 5, n4 = (idx & 31) * 4;
            *(uint4*)&SB[buf][kp * 136 + n4] = ub[p];
        }
    };
    auto COMP = [&](int buf) {
        u32 sa0 = shaddr(&SA[buf][(wm + lrow) * 20 + lcol]);
        #pragma unroll
        for (int s = 0; s < 2; s++) {
            int kp = 8 * s + t;
            u32 af[4][4], bf[4][2];
            #pragma unroll
            for (int i = 0; i < 4; i++)
                ldsm4(af[i], sa0 + ((16 * i * 20 + 8 * s) << 2));
            #pragma unroll
            for (int j = 0; j < 4; j++) {
                int n = wn + 8 * j + g;
                bf[j][0] = SB[buf][kp * 136 + n];
                bf[j][1] = SB[buf][(kp + 4) * 136 + n];
            }
            #pragma unroll
            for (int i = 0; i < 4; i++)
                #pragma unroll
                for (int j = 0; j < 4; j++) mmab(acc[i][j], af[i], bf[j]);
        }
    };
    LOAD(0); STS(0); __syncthreads();
    for (int it = 0; it < 4; it++) {
        if (it + 1 < 4) LOAD((it + 1) * 32);
        COMP(it & 1);
        if (it + 1 < 4) { STS((it + 1) & 1); __syncthreads(); }
    }
    #pragma unroll
    for (int i = 0; i < 4; i++) {
        int row = row0 + wm + 16 * i + g;
        #pragma unroll
        for (int j = 0; j < 4; j++) {
            int col = col0 + wn + 8 * j + 2 * t;
            float2 bb = *(const float2*)&bout[col];
            float2 x0 = *(const float2*)&x[(size_t)row*DD + col];
            float2 x1 = *(const float2*)&x[(size_t)(row+8)*DD + col];
            *(float2*)&out[(size_t)row*DD + col] =
                make_float2(acc[i][j][0] + bb.x + x0.x, acc[i][j][1] + bb.y + x0.y);
            *(float2*)&out[(size_t)(row+8)*DD + col] =
                make_float2(acc[i][j][2] + bb.x + x1.x, acc[i][j][3] + bb.y + x1.y);
        }
    }
}

// pinv bmm (R11-proven, 24 launches)
__global__ __launch_bounds__(256) void bmm_mma(const float* __restrict__ A,
                                               const float* __restrict__ Bm,
                                               float* __restrict__ C,
                                               float alpha, float beta, float gam) {
    __shared__ u32 SA[2][64*20];
    __shared__ u32 SB[2][16*72];
    int bh = blockIdx.z;
    size_t base = (size_t)bh * MM * MM;
    int i0 = blockIdx.x * 64, j0 = blockIdx.y * 64;
    int tid = threadIdx.x;
    int lane = tid & 31, wid = tid >> 5;
    int g = lane >> 2, t = lane & 3;
    int wm = (wid & 3) * 16, wn = (wid >> 2) * 32;
    int mi = lane >> 3;
    int lrow = (lane & 7) + (mi & 1) * 8;
    int lcol = (mi >> 1) * 4;
    float acc[4][4];
    #pragma unroll
    for (int j = 0; j < 4; j++) for (int u = 0; u < 4; u++) acc[j][u] = 0.f;
    int am = tid >> 2, akg = tid & 3;
    int bkp = tid >> 4, bn4 = (tid & 15) * 4;
    float4 a1, a2, b1, b2;
    auto LOAD = [&](int kt) {
        const float* src = &A[base + (size_t)(i0 + am) * MM + kt + akg * 8];
        a1 = *(const float4*)src;
        a2 = *(const float4*)(src + 4);
        int k = kt + bkp * 2;
        b1 = *(const float4*)&Bm[base + (size_t)k * MM + j0 + bn4];
        b2 = *(const float4*)&Bm[base + (size_t)(k + 1) * MM + j0 + bn4];
    };
    auto STS = [&](int buf) {
        *(uint4*)&SA[buf][am * 20 + akg * 4] = pkA(a1, a2);
        *(uint4*)&SB[buf][bkp * 72 + bn4] = pkB(b1, b2);
    };
    auto COMP = [&](int buf) {
        u32 sa0 = shaddr(&SA[buf][(wm + lrow) * 20 + lcol]);
        #pragma unroll
        for (int s = 0; s < 2; s++) {
            int kp = 8 * s + t;
            u32 af[4], bf[4][2];
            ldsm4(af, sa0 + ((8 * s) << 2));
            #pragma unroll
            for (int j = 0; j < 4; j++) {
                int n = wn + 8 * j + g;
                bf[j][0] = SB[buf][kp * 72 + n];
                bf[j][1] = SB[buf][(kp + 4) * 72 + n];
            }
            #pragma unroll
            for (int j = 0; j < 4; j++) mmab(acc[j], af, bf[j]);
        }
    };
    LOAD(0); STS(0); __syncthreads();
    for (int it = 0; it < 8; it++) {
        if (it + 1 < 8) LOAD((it + 1) * 32);
        COMP(it & 1);
        if (it + 1 < 8) { STS((it + 1) & 1); __syncthreads(); }
    }
    #pragma unroll
    for (int j = 0; j < 4; j++) {
        #pragma unroll
        for (int u = 0; u < 4; u++) {
            int row = i0 + wm + g + (u >> 1) * 8;
            int col = j0 + wn + 8 * j + 2 * t + (u & 1);
            float r = alpha * acc[j][u];
            if (beta != 0.f) r += beta * A[base + (size_t)row * MM + col];
            if (row == col) r += gam;
            C[base + (size_t)row * MM + col] = r;
        }
    }
}

// NN, N=64 tf32 (W2 = Z @ a3v only)
__global__ __launch_bounds__(128) void nn64_mma(const float* __restrict__ A,
                                                const float* __restrict__ B,
                                                float* __restrict__ C,
                                                int lda, size_t aBatch, size_t bBatch,
                                                size_t cBatch, int kchunk) {
    __shared__ unsigned As[64*36];
    __shared__ unsigned Bs[32*72];
    int bh = blockIdx.z;
    int m0 = blockIdx.x * 64;
    const float* Ab = A + (size_t)bh * aBatch + (size_t)m0 * lda;
    const float* Bb = B + (size_t)bh * bBatch;
    int tid = threadIdx.x;
    int lane = tid & 31, wid = tid >> 5;
    int g = lane >> 2, t = lane & 3;
    int wm = (wid & 1) * 32, wn = (wid >> 1) * 32;
    float acc[2][4][4];
    #pragma unroll
    for (int i = 0; i < 2; i++) for (int j = 0; j < 4; j++) for (int u = 0; u < 4; u++) acc[i][j][u] = 0.f;
    int iters = kchunk / 32;
    for (int it = 0; it < iters; it++) {
        #pragma unroll
        for (int p = 0; p < 4; p++) {
            int idx = tid + p * 128; int m = idx >> 3, c = (idx & 7) * 4;
            float4 v = *(const float4*)&Ab[(size_t)m * lda + it*32 + c];
            *(uint4*)&As[m*36+c] = make_uint4(f2tf(v.x), f2tf(v.y), f2tf(v.z), f2tf(v.w));
        }
        #pragma unroll
        for (int p = 0; p < 4; p++) {
            int idx = tid + p * 128; int k = idx >> 4, c = (idx & 15) * 4;
            float4 v = *(const float4*)&Bb[(size_t)(it*32 + k) * 64 + c];
            *(uint4*)&Bs[k*72+c] = make_uint4(f2tf(v.x), f2tf(v.y), f2tf(v.z), f2tf(v.w));
        }
        __syncthreads();
        #pragma unroll
        for (int s = 0; s < 4; s++) {
            unsigned af[2][4], bf[4][2];
            #pragma unroll
            for (int i = 0; i < 2; i++) {
                const unsigned* p = &As[(wm + 16*i + g)*36 + 8*s + t];
                af[i][0] = p[0]; af[i][1] = p[288]; af[i][2] = p[4]; af[i][3] = p[292];
            }
            #pragma unroll
            for (int j = 0; j < 4; j++) {
                const unsigned* p = &Bs[(8*s + t)*72 + wn + 8*j + g];
                bf[j][0] = p[0]; bf[j][1] = p[288];
            }
            #pragma unroll
            for (int i = 0; i < 2; i++)
                #pragma unroll
                for (int j = 0; j < 4; j++) mma8(acc[i][j], af[i], bf[j]);
        }
        __syncthreads();
    }
    float* Cb = C + (size_t)bh * cBatch + (size_t)m0 * 64;
    #pragma unroll
    for (int i = 0; i < 2; i++) {
        int row = wm + 16*i + g;
        #pragma unroll
        for (int j = 0; j < 4; j++) {
            int col = wn + 8*j + 2*t;
            Cb[(size_t)row*64 + col]       = acc[i][j][0];
            Cb[(size_t)row*64 + col+1]     = acc[i][j][1];
            Cb[(size_t)(row+8)*64 + col]   = acc[i][j][2];
            Cb[(size_t)(row+8)*64 + col+1] = acc[i][j][3];
        }
    }
}

// ---------- fused flash kernels ----------
__global__ __launch_bounds__(256) void attn3_kernel() {
    extern __shared__ u32 smu[];
    u32* QS = smu;
    u32* KS = QS + 64*36;
    u32* VS = KS + 128*36;
    float* SS = (float*)(VS + 64*72);
    u32* PS = (u32*)(SS + 64*132);
    float* sm_m = (float*)(PS + 64*68);
    float* sm_l = sm_m + 64;
    float* sm_sc = sm_l + 64;
    int tid = threadIdx.x;
    int r0 = blockIdx.x * 64, sp = blockIdx.y, bh = blockIdx.z;
    int lane = tid & 31, wid = tid >> 5;
    int g = lane >> 2, t = lane & 3;
    int mi = lane >> 3;
    int lrow = (lane & 7) + (mi & 1) * 8;
    int lcol = (mi >> 1) * 4;
    #pragma unroll
    for (int p = 0; p < 2; p++) {
        int idx = tid + p * 256; int m = idx >> 3, kg = idx & 7;
        const float* src = &g_ql[((size_t)bh * MM + r0 + m) * DH + kg * 8];
        *(uint4*)&QS[m*36 + kg*4] = pkA(*(const float4*)src, *(const float4*)(src + 4));
    }
    if (tid < 64) { sm_m[tid] = -1e30f; sm_l[tid] = 0.f; }
    int m0 = (wid & 3) * 16;
    int n0s = (wid >> 2) * 64;
    int n0o = (wid >> 2) * 32;
    float acco[4][4];
    #pragma unroll
    for (int j = 0; j < 4; j++) for (int u = 0; u < 4; u++) acco[j][u] = 0.f;
    __syncthreads();
    for (int ch = 0; ch < 8; ch++) {
        int k0 = sp * 1024 + ch * 128;
        #pragma unroll
        for (int p = 0; p < 4; p++) {
            int idx = tid + p * 256; int key = idx >> 3, kg = idx & 7;
            *(uint4*)&KS[key*36 + kg*4] =
                *(const uint4*)&g_kh[((size_t)bh * NSEQ + k0 + key) * 32 + kg * 4];
        }
        #pragma unroll
        for (int p = 0; p < 4; p++) {
            int idx = tid + p * 256; int kp = idx >> 4, n4 = (idx & 15) * 4;
            uint2 va = *(const uint2*)&g_vh[((size_t)bh * NSEQ + k0 + 2*kp) * 32 + (idx & 15) * 2];
            uint2 vb = *(const uint2*)&g_vh[((size_t)bh * NSEQ + k0 + 2*kp + 1) * 32 + (idx & 15) * 2];
            VS[kp*72 + n4 + 0] = (va.x & 0xFFFFu) | (vb.x << 16);
            VS[kp*72 + n4 + 1] = (va.x >> 16) | (vb.x & 0xFFFF0000u);
            VS[kp*72 + n4 + 2] = (va.y & 0xFFFFu) | (vb.y << 16);
            VS[kp*72 + n4 + 3] = (va.y >> 16) | (vb.y & 0xFFFF0000u);
        }
        __syncthreads();
        float accs[8][4];
        #pragma unroll
        for (int j = 0; j < 8; j++) for (int u = 0; u < 4; u++) accs[j][u] = 0.f;
        u32 qa = shaddr(&QS[(m0 + lrow)*36 + lcol]);
        u32 ka = shaddr(&KS[(n0s + lrow)*36 + lcol]);
        #pragma unroll
        for (int s = 0; s < 4; s++) {
            u32 af[4];
            ldsm4(af, qa + ((8 * s) << 2));
            #pragma unroll
            for (int jj = 0; jj < 4; jj++) {
                u32 bfr[4];
                ldsm4(bfr, ka + ((16*jj*36 + 8*s) << 2));
                u32 b0[2] = {bfr[0], bfr[2]};
                u32 b1[2] = {bfr[1], bfr[3]};
                mmab(accs[2*jj], af, b0);
                mmab(accs[2*jj+1], af, b1);
            }
        }
        #pragma unroll
        for (int j = 0; j < 8; j++) {
            int col = n0s + 8*j + 2*t;
            *(float2*)&SS[(m0+g)*132 + col]   = make_float2(accs[j][0], accs[j][1]);
            *(float2*)&SS[(m0+g+8)*132 + col] = make_float2(accs[j][2], accs[j][3]);
        }
        __syncthreads();
        {
            int row = tid >> 2, t2 = tid & 3;
            float* Sr = &SS[row*132 + t2*32];
            float cmax = -1e30f;
            #pragma unroll
            for (int c = 0; c < 32; c++) cmax = fmaxf(cmax, Sr[c]);
            cmax = fmaxf(cmax, __shfl_xor_sync(0xffffffffu, cmax, 1));
            cmax = fmaxf(cmax, __shfl_xor_sync(0xffffffffu, cmax, 2));
            float mold = sm_m[row];
            float mnew = fmaxf(mold, cmax);
            float csum = 0.f;
            #pragma unroll
            for (int c = 0; c < 32; c += 2) {
                float pv0 = __expf(Sr[c] - mnew);
                float pv1 = __expf(Sr[c+1] - mnew);
                csum += pv0 + pv1;
                PS[row*68 + t2*16 + (c >> 1)] = pk2(pv0, pv1);
            }
            csum += __shfl_xor_sync(0xffffffffu, csum, 1);
            csum += __shfl_xor_sync(0xffffffffu, csum, 2);
            if (t2 == 0) {
                float scv = __expf(mold - mnew);
                sm_sc[row] = scv;
                sm_l[row] = sm_l[row] * scv + csum;
                sm_m[row] = mnew;
            }
        }
        __syncthreads();
        {
            float s0 = sm_sc[m0 + g], s1 = sm_sc[m0 + g + 8];
            #pragma unroll
            for (int j = 0; j < 4; j++) {
                acco[j][0] *= s0; acco[j][1] *= s0;
                acco[j][2] *= s1; acco[j][3] *= s1;
            }
            u32 pa = shaddr(&PS[(m0 + lrow)*68 + lcol]);
            #pragma unroll
            for (int s = 0; s < 8; s++) {
                u32 af[4];
                ldsm4(af, pa + ((8 * s) << 2));
                #pragma unroll
                for (int j = 0; j < 4; j++) {
                    int n = n0o + 8*j + g;
                    u32 bf2[2];
                    bf2[0] = VS[(8*s + t)*72 + n];
                    bf2[1] = VS[(8*s + t + 4)*72 + n];
                    mmab(acco[j], af, bf2);
                }
            }
        }
        __syncthreads();
    }
    size_t pb = ((size_t)(bh*NSP + sp) * MM + r0);
    #pragma unroll
    for (int j = 0; j < 4; j++) {
        int col = n0o + 8*j + 2*t;
        *(float2*)&g_part[(pb + m0 + g) * DH + col]     = make_float2(acco[j][0], acco[j][1]);
        *(float2*)&g_part[(pb + m0 + g + 8) * DH + col] = make_float2(acco[j][2], acco[j][3]);
    }
    if (tid < 64) {
        g_m[(bh*NSP + sp) * MM + r0 + tid] = sm_m[tid];
        g_l[(bh*NSP + sp) * MM + r0 + tid] = sm_l[tid];
    }
}

__global__ void attn_combine() {
    int idx = blockIdx.x * 256 + threadIdx.x;
    int bh = idx >> 14, rem = idx & 16383, row = rem >> 6, d = rem & 63;
    float ms = -1e30f;
    #pragma unroll
    for (int s = 0; s < NSP; s++) ms = fmaxf(ms, g_m[(bh*NSP+s)*MM + row]);
    float num = 0.f, den = 0.f;
    #pragma unroll
    for (int s = 0; s < NSP; s++) {
        float e = __expf(g_m[(bh*NSP+s)*MM + row] - ms);
        num += g_part[((size_t)(bh*NSP+s)*MM + row)*DH + d] * e;
        den += g_l[(bh*NSP+s)*MM + row] * e;
    }
    g_a3v[((size_t)bh*MM + row)*DH + d] = num / den;
}

// attn1: 512 threads (16 warps) for latency hiding at 1 CTA/SM
__global__ __launch_bounds__(512) void attn1_kernel(const float* __restrict__ wres) {
    extern __shared__ u32 smu[];
    u32* QS  = smu;                     // [64][36]
    u32* KLS = QS + 64*36;              // [256][36]
    u32* W2S = KLS + 256*36;            // [128][72]
    float* SS = (float*)(W2S + 128*72); // [64][264]; VC aliases SS [96][68]
    u32* PS = (u32*)(SS + 64*264);      // [64][132]
    float* CONV = (float*)(PS + 64*132);// [64][66]
    float* sm_l = CONV + 64*66;
    float* wl = sm_l + 64;
    float* VC = SS;
    int tid = threadIdx.x;
    int r0 = blockIdx.x * 64, bh = blockIdx.y;
    int lane = tid & 31, wid = tid >> 5;
    int g = lane >> 2, t = lane & 3;
    int mi = lane >> 3;
    int lrow = (lane & 7) + (mi & 1) * 8;
    int lcol = (mi >> 1) * 4;
    if (tid < KERN) wl[tid] = wres[(bh & 1) * KERN + tid];
    // Q: 512 uint4 -> 1 per thread
    {
        int m = tid >> 3, kg = tid & 7;
        *(uint4*)&QS[m*36 + kg*4] =
            *(const uint4*)&g_qh[((size_t)bh * NSEQ + r0 + m) * 32 + kg * 4];
    }
    // KLS: 2048 uint4 -> 4 per thread
    #pragma unroll
    for (int p = 0; p < 4; p++) {
        int idx = tid + p * 512; int m = idx >> 3, kg = idx & 7;
        const float* src = &g_kl[((size_t)bh * MM + m) * DH + kg * 8];
        *(uint4*)&KLS[m*36 + kg*4] = pkA(*(const float4*)src, *(const float4*)(src + 4));
    }
    // W2S: 2048 uint4 -> 4 per thread
    #pragma unroll
    for (int p = 0; p < 4; p++) {
        int idx = tid + p * 512; int kp = idx >> 4, n4 = (idx & 15) * 4;
        const float* s0 = &g_w2[((size_t)bh * MM + 2*kp) * DH + n4];
        *(uint4*)&W2S[kp*72 + n4] = pkB(*(const float4*)s0, *(const float4*)(s0 + DH));
    }
    // VC: 1536 float4 -> 3 per thread
    #pragma unroll
    for (int p = 0; p < 3; p++) {
        int idx = tid + p * 512; int li = idx >> 4, d4 = (idx & 15) * 4;
        int n = r0 - 16 + li;
        float4 val = make_float4(0.f, 0.f, 0.f, 0.f);
        if (n >= 0 && n < NSEQ) {
            uint2 v2 = *(const uint2*)&g_vh[((size_t)bh * NSEQ + n) * 32 + (idx & 15) * 2];
            val = make_float4(blo(v2.x), bhi(v2.x), blo(v2.y), bhi(v2.y));
        }
        *(float4*)&VC[li * 68 + d4] = val;
    }
    __syncthreads();
    // conv: 64 rows x 64 cols, 512 threads -> 8 values each
    {
        int rr = tid >> 3, ds = (tid & 7) * 8;
        #pragma unroll
        for (int d4 = 0; d4 < 2; d4++) {
            float4 a4 = make_float4(0.f, 0.f, 0.f, 0.f);
            #pragma unroll
            for (int tap = 0; tap < KERN; tap++) {
                float w = wl[tap];
                float4 vv = *(const float4*)&VC[(rr + tap) * 68 + ds + d4 * 4];
                a4.x += w * vv.x; a4.y += w * vv.y; a4.z += w * vv.z; a4.w += w * vv.w;
            }
            CONV[rr * 66 + ds + d4 * 4 + 0] = a4.x;
            CONV[rr * 66 + ds + d4 * 4 + 1] = a4.y;
            CONV[rr * 66 + ds + d4 * 4 + 2] = a4.z;
            CONV[rr * 66 + ds + d4 * 4 + 3] = a4.w;
        }
    }
    // S-gemm: 16 warps -> 4 m-tiles x 4 col-groups of 64
    int m0 = (wid & 3) * 16;
    int n0s = (wid >> 2) * 64;
    float accs[8][4];
    #pragma unroll
    for (int j = 0; j < 8; j++) for (int u = 0; u < 4; u++) accs[j][u] = 0.f;
    u32 qa = shaddr(&QS[(m0 + lrow)*36 + lcol]);
    u32 ka = shaddr(&KLS[(n0s + lrow)*36 + lcol]);
    #pragma unroll
    for (int s = 0; s < 4; s++) {
        u32 af[4];
        ldsm4(af, qa + ((8 * s) << 2));
        #pragma unroll
        for (int jj = 0; jj < 4; jj++) {
            u32 bfr[4];
            ldsm4(bfr, ka + ((16*jj*36 + 8*s) << 2));
            u32 b0[2] = {bfr[0], bfr[2]};
            u32 b1[2] = {bfr[1], bfr[3]};
            mmab(accs[2*jj], af, b0);
            mmab(accs[2*jj+1], af, b1);
        }
    }
    __syncthreads();   // conv VC reads done before SS overwrite
    #pragma unroll
    for (int j = 0; j < 8; j++) {
        int col = n0s + 8*j + 2*t;
        *(float2*)&SS[(m0+g)*264 + col]   = make_float2(accs[j][0], accs[j][1]);
        *(float2*)&SS[(m0+g+8)*264 + col] = make_float2(accs[j][2], accs[j][3]);
    }
    __syncthreads();
    // softmax: row = tid>>3 (64 rows x 8 lanes), 32 cols each
    {
        int row = tid >> 3, t2 = tid & 7;
        float* Sr = &SS[row*264 + t2*32];
        float cmax = -1e30f;
        #pragma unroll
        for (int c = 0; c < 32; c++) cmax = fmaxf(cmax, Sr[c]);
        cmax = fmaxf(cmax, __shfl_xor_sync(0xffffffffu, cmax, 1));
        cmax = fmaxf(cmax, __shfl_xor_sync(0xffffffffu, cmax, 2));
        cmax = fmaxf(cmax, __shfl_xor_sync(0xffffffffu, cmax, 4));
        float csum = 0.f;
        #pragma unroll
        for (int c = 0; c < 32; c += 2) {
            float pv0 = __expf(Sr[c] - cmax);
            float pv1 = __expf(Sr[c+1] - cmax);
            csum += pv0 + pv1;
            PS[row*132 + t2*16 + (c >> 1)] = pk2(pv0, pv1);
        }
        csum += __shfl_xor_sync(0xffffffffu, csum, 1);
        csum += __shfl_xor_sync(0xffffffffu, csum, 2);
        csum += __shfl_xor_sync(0xffffffffu, csum, 4);
        if (t2 == 0) sm_l[row] = csum;
    }
    __syncthreads();
    // P-gemm: 16 warps -> 4 m-tiles x 4 out-col groups of 16
    int n0o = (wid >> 2) * 16;
    float acco[2][4];
    #pragma unroll
    for (int j = 0; j < 2; j++) for (int u = 0; u < 4; u++) acco[j][u] = 0.f;
    u32 pa = shaddr(&PS[(m0 + lrow)*132 + lcol]);
    #pragma unroll
    for (int s = 0; s < 16; s++) {
        u32 af[4];
        ldsm4(af, pa + ((8 * s) << 2));
        #pragma unroll
        for (int j = 0; j < 2; j++) {
            int n = n0o + 8*j + g;
            u32 bf2[2];
            bf2[0] = W2S[(8*s + t)*72 + n];
            bf2[1] = W2S[(8*s + t + 4)*72 + n];
            mmab(acco[j], af, bf2);
        }
    }
    float il0 = 1.f / sm_l[m0 + g], il1 = 1.f / sm_l[m0 + g + 8];
    size_t ob = (size_t)bh * NSEQ + r0;
    int row0l = m0 + g, row1l = m0 + g + 8;
    #pragma unroll
    for (int j = 0; j < 2; j++) {
        int col = n0o + 8*j + 2*t;
        int dp = col >> 1;
        float v00 = acco[j][0]*il0 + CONV[row0l*66 + col];
        float v01 = acco[j][1]*il0 + CONV[row0l*66 + col + 1];
        float v10 = acco[j][2]*il1 + CONV[row1l*66 + col];
        float v11 = acco[j][3]*il1 + CONV[row1l*66 + col + 1];
        g_out1h[(ob + row0l) * 32 + dp] = pk2(v00, v01);
        g_out1h[(ob + row1l) * 32 + dp] = pk2(v10, v11);
    }
}

// ---------------- launch ----------------
extern "C" void kernel_launch(void* const* d_in, const int* in_sizes, int n_in,
                              void* d_out, int out_size) {
    const float* x     = (const float*)d_in[0];
    const float* gamma = (const float*)d_in[1];
    const float* beta  = (const float*)d_in[2];
    const float* wqkv  = (const float*)d_in[3];
    const float* wout  = (const float*)d_in[4];
    const float* bout  = (const float*)d_in[5];
    const float* wres  = (const float*)d_in[6];
    float* out = (float*)d_out;

    float *pA2, *pXZ, *pT1, *pT2, *pZA, *pZB, *pA3V, *pW2;
    cudaGetSymbolAddress((void**)&pA2, g_a2);
    cudaGetSymbolAddress((void**)&pXZ, g_xz);
    cudaGetSymbolAddress((void**)&pT1, g_t1);
    cudaGetSymbolAddress((void**)&pT2, g_t2);
    cudaGetSymbolAddress((void**)&pZA, g_za);
    cudaGetSymbolAddress((void**)&pZB, g_zb);
    cudaGetSymbolAddress((void**)&pA3V, g_a3v);
    cudaGetSymbolAddress((void**)&pW2, g_w2);

    cudaFuncSetAttribute(attn3_kernel, cudaFuncAttributeMaxDynamicSharedMemorySize, 98048);
    cudaFuncSetAttribute(attn1_kernel, cudaFuncAttributeMaxDynamicSharedMemorySize, 201664);

    init_kernel<<<1, 1>>>();
    prepack_kernel<<<512, 256>>>(wqkv, wout);
    ln_kernel<<<TOK, 128>>>(x, gamma, beta);
    qkv_mma<<<dim3(TOK / 128, 3), 256>>>();
    landmark_kernel<<<dim3(BH, MM / 4), 256>>>();
    sim2_kernel<<<BH * MM, 256>>>();
    absmax_kernel<<<dim3(BH, 2), 256>>>();
    zinit_kernel<<<BH * MM, 256>>>();

    float* zc = pZA;
    float* zn = pZB;
    for (int it = 0; it < 6; it++) {
        bmm_mma<<<dim3(4, 4, BH), 256>>>(pA2, zc, pXZ, 1.f, 0.f, 0.f);
        bmm_mma<<<dim3(4, 4, BH), 256>>>(pXZ, pXZ, pT1, 1.f, -7.f, 15.f);
        bmm_mma<<<dim3(4, 4, BH), 256>>>(pXZ, pT1, pT2, -1.f, 0.f, 13.f);
        bmm_mma<<<dim3(4, 4, BH), 256>>>(zc, pT2, zn, 0.25f, 0.f, 0.f);
        float* t = zc; zc = zn; zn = t;
    }

    attn3_kernel<<<dim3(4, NSP, BH), 256, 98048>>>();
    attn_combine<<<512, 256>>>();
    nn64_mma<<<dim3(4, 1, BH), 128>>>(zc, pA3V, pW2, MM,
        (size_t)MM * MM, (size_t)MM * 64, (size_t)MM * 64, MM);
    attn1_kernel<<<dim3(NSEQ / 64, BH), 512, 201664>>>(wres);
    outgemm_mma<<<dim3(TOK / 128, 4), 256>>>(x, bout, out);
}

// round 17
// speedup vs baseline: 1.0297x; 1.0297x over previous
#include <cuda_runtime.h>
#include <math.h>

#define BB 4
#define NSEQ 8192
#define DD 512
#define HH 2
#define DH 64
#define INNER 128
#define MM 256
#define LLM 32
#define BH (BB*HH)
#define TOK (BB*NSEQ)
#define KERN 33
#define NSP 8

typedef unsigned u32;

__device__ u32   g_xnh[(size_t)TOK*256];
__device__ u32   g_wqkvh[256*384];              // w_qkv bf16x2 [k/2][n]
__device__ u32   g_wouth[64*512];               // w_out bf16x2 [k/2][n]
__device__ u32   g_qh[(size_t)BH*NSEQ*32];
__device__ u32   g_kh[(size_t)BH*NSEQ*32];
__device__ u32   g_vh[(size_t)BH*NSEQ*32];
__device__ float g_ql[BH*MM*DH];
__device__ float g_kl[BH*MM*DH];
__device__ float g_a2[BH*MM*MM];
__device__ float g_xz[BH*MM*MM];
__device__ float g_t1[BH*MM*MM];
__device__ float g_t2[BH*MM*MM];
__device__ float g_za[BH*MM*MM];
__device__ float g_zb[BH*MM*MM];
__device__ float g_a3v[BH*MM*DH];
__device__ float g_w2[BH*MM*DH];
__device__ u32   g_out1h[(size_t)BH*NSEQ*32];
__device__ float g_part[BH*NSP*MM*DH];
__device__ float g_m[BH*NSP*MM];
__device__ float g_l[BH*NSP*MM];
__device__ unsigned g_max0, g_max1;

// ---- helpers ----
__device__ __forceinline__ unsigned f2tf(float f) {
    unsigned r; asm("cvt.rna.tf32.f32 %0, %1;" : "=r"(r) : "f"(f)); return r;
}
__device__ __forceinline__ void mma8(float* c, const unsigned* a, const unsigned* b) {
    asm volatile("mma.sync.aligned.m16n8k8.row.col.f32.tf32.tf32.f32 "
        "{%0,%1,%2,%3}, {%4,%5,%6,%7}, {%8,%9}, {%0,%1,%2,%3};"
        : "+f"(c[0]), "+f"(c[1]), "+f"(c[2]), "+f"(c[3])
        : "r"(a[0]), "r"(a[1]), "r"(a[2]), "r"(a[3]), "r"(b[0]), "r"(b[1]));
}
__device__ __forceinline__ u32 pk2(float lo, float hi) {
    u32 r; asm("cvt.rn.bf16x2.f32 %0, %2, %1;" : "=r"(r) : "f"(lo), "f"(hi)); return r;
}
__device__ __forceinline__ void mmab(float* c, const u32* a, const u32* b) {
    asm volatile("mma.sync.aligned.m16n8k16.row.col.f32.bf16.bf16.f32 "
        "{%0,%1,%2,%3}, {%4,%5,%6,%7}, {%8,%9}, {%0,%1,%2,%3};"
        : "+f"(c[0]), "+f"(c[1]), "+f"(c[2]), "+f"(c[3])
        : "r"(a[0]), "r"(a[1]), "r"(a[2]), "r"(a[3]), "r"(b[0]), "r"(b[1]));
}
__device__ __forceinline__ uint4 pkA(float4 v1, float4 v2) {
    return make_uint4(pk2(v1.x,v1.y), pk2(v1.z,v1.w), pk2(v2.x,v2.y), pk2(v2.z,v2.w));
}
__device__ __forceinline__ uint4 pkB(float4 r1, float4 r2) {
    return make_uint4(pk2(r1.x,r2.x), pk2(r1.y,r2.y), pk2(r1.z,r2.z), pk2(r1.w,r2.w));
}
__device__ __forceinline__ void ldsm4(u32* r, u32 addr) {
    asm volatile("ldmatrix.sync.aligned.m8n8.x4.shared.b16 {%0,%1,%2,%3}, [%4];"
        : "=r"(r[0]), "=r"(r[1]), "=r"(r[2]), "=r"(r[3]) : "r"(addr));
}
__device__ __forceinline__ u32 shaddr(const void* p) {
    return (u32)__cvta_generic_to_shared(p);
}
__device__ __forceinline__ float blo(u32 w) { return __uint_as_float(w << 16); }
__device__ __forceinline__ float bhi(u32 w) { return __uint_as_float(w & 0xFFFF0000u); }

__global__ void init_kernel() { g_max0 = 0u; g_max1 = 0u; }

__global__ void prepack_kernel(const float* __restrict__ wqkv, const float* __restrict__ wout) {
    int idx = blockIdx.x * 256 + threadIdx.x;
    if (idx < 256 * 384) {
        int kp = idx / 384, n = idx % 384;
        g_wqkvh[idx] = pk2(wqkv[(size_t)(2*kp) * 384 + n], wqkv[(size_t)(2*kp+1) * 384 + n]);
    } else {
        int j = idx - 256 * 384;
        int kp = j / 512, n = j % 512;
        g_wouth[j] = pk2(wout[(size_t)(2*kp) * 512 + n], wout[(size_t)(2*kp+1) * 512 + n]);
    }
}

__global__ __launch_bounds__(128) void ln_kernel(const float* __restrict__ x,
                                                 const float* __restrict__ gamma,
                                                 const float* __restrict__ beta) {
    int t = blockIdx.x, tid = threadIdx.x;
    const float4* xr = (const float4*)(x + (size_t)t * DD);
    float4 v = xr[tid];
    float s  = v.x + v.y + v.z + v.w;
    float sq = v.x*v.x + v.y*v.y + v.z*v.z + v.w*v.w;
    __shared__ float sb[8];
    #pragma unroll
    for (int o = 16; o; o >>= 1) {
        s  += __shfl_xor_sync(0xffffffffu, s, o);
        sq += __shfl_xor_sync(0xffffffffu, sq, o);
    }
    int w = tid >> 5, l = tid & 31;
    if (l == 0) { sb[w] = s; sb[4 + w] = sq; }
    __syncthreads();
    if (tid == 0) { sb[0] = sb[0]+sb[1]+sb[2]+sb[3]; sb[4] = sb[4]+sb[5]+sb[6]+sb[7]; }
    __syncthreads();
    float mu  = sb[0] * (1.f / DD);
    float var = sb[4] * (1.f / DD) - mu * mu;
    float rs  = rsqrtf(var + 1e-5f);
    float4 g4 = ((const float4*)gamma)[tid];
    float4 b4 = ((const float4*)beta)[tid];
    float4 o;
    o.x = (v.x - mu) * rs * g4.x + b4.x;
    o.y = (v.y - mu) * rs * g4.y + b4.y;
    o.z = (v.z - mu) * rs * g4.z + b4.z;
    o.w = (v.w - mu) * rs * g4.w + b4.w;
    uint2 pr = make_uint2(pk2(o.x, o.y), pk2(o.z, o.w));
    *(uint2*)&g_xnh[(size_t)t * 256 + tid * 2] = pr;
}

__global__ __launch_bounds__(256) void landmark_kernel() {
    __shared__ float4 rq[256], rk[256];
    int bh = blockIdx.x, m0 = blockIdx.y * 4;
    int tid = threadIdx.x;
    int l = tid >> 6, t2 = tid & 63;
    int rseg = t2 >> 4, dp = (t2 & 15) * 2;
    int m = m0 + l;
    size_t base = ((size_t)bh * NSEQ + m * LLM + rseg * 8) * 32 + dp;
    float4 sq = make_float4(0.f,0.f,0.f,0.f), sk = sq;
    #pragma unroll
    for (int i = 0; i < 8; i++) {
        uint2 a = *(const uint2*)&g_qh[base + (size_t)i * 32];
        uint2 b = *(const uint2*)&g_kh[base + (size_t)i * 32];
        sq.x += blo(a.x); sq.y += bhi(a.x); sq.z += blo(a.y); sq.w += bhi(a.y);
        sk.x += blo(b.x); sk.y += bhi(b.x); sk.z += blo(b.y); sk.w += bhi(b.y);
    }
    rq[tid] = sq; rk[tid] = sk;
    __syncthreads();
    if (rseg == 0) {
        #pragma unroll
        for (int u = 1; u < 4; u++) {
            float4 a = rq[tid + u * 16], b = rk[tid + u * 16];
            sq.x += a.x; sq.y += a.y; sq.z += a.z; sq.w += a.w;
            sk.x += b.x; sk.y += b.y; sk.z += b.z; sk.w += b.w;
        }
        const float inv = 1.f / LLM;
        sq.x *= inv; sq.y *= inv; sq.z *= inv; sq.w *= inv;
        sk.x *= inv; sk.y *= inv; sk.z *= inv; sk.w *= inv;
        *(float4*)&g_ql[(bh * MM + m) * DH + dp * 2] = sq;
        *(float4*)&g_kl[(bh * MM + m) * DH + dp * 2] = sk;
    }
}

__global__ __launch_bounds__(256) void sim2_kernel() {
    int bh = blockIdx.x >> 8, i = blockIdx.x & 255;
    int tid = threadIdx.x;
    __shared__ float qs[DH];
    __shared__ float red[8];
    if (tid < DH) qs[tid] = g_ql[(bh * MM + i) * DH + tid];
    __syncthreads();
    const float* kr = &g_kl[(bh * MM + tid) * DH];
    float s = 0.f;
    #pragma unroll
    for (int d = 0; d < DH; d += 4) {
        float4 kv = *(const float4*)&kr[d];
        s += qs[d]*kv.x + qs[d+1]*kv.y + qs[d+2]*kv.z + qs[d+3]*kv.w;
    }
    float m = s;
    #pragma unroll
    for (int o = 16; o; o >>= 1) m = fmaxf(m, __shfl_xor_sync(0xffffffffu, m, o));
    int w = tid >> 5, l = tid & 31;
    if (l == 0) red[w] = m;
    __syncthreads();
    if (w == 0) {
        float t = red[l & 7];
        #pragma unroll
        for (int o = 4; o; o >>= 1) t = fmaxf(t, __shfl_xor_sync(0xffffffffu, t, o));
        if (l == 0) red[0] = t;
    }
    __syncthreads();
    m = red[0];
    __syncthreads();
    float e = __expf(s - m);
    float su = e;
    #pragma unroll
    for (int o = 16; o; o >>= 1) su += __shfl_xor_sync(0xffffffffu, su, o);
    if (l == 0) red[w] = su;
    __syncthreads();
    if (w == 0) {
        float t = red[l & 7];
        #pragma unroll
        for (int o = 4; o; o >>= 1) t += __shfl_xor_sync(0xffffffffu, t, o);
        if (l == 0) red[0] = t;
    }
    __syncthreads();
    g_a2[((size_t)bh * MM + i) * MM + tid] = e / red[0];
}

__global__ __launch_bounds__(256) void absmax_kernel() {
    int bh = blockIdx.x, mode = blockIdx.y, tid = threadIdx.x;
    const float* A = &g_a2[(size_t)bh * MM * MM];
    float s = 0.f;
    if (mode == 0) { for (int j = 0; j < MM; j++) s += fabsf(A[tid * MM + j]); }
    else           { for (int i = 0; i < MM; i++) s += fabsf(A[i * MM + tid]); }
    float m = s;
    #pragma unroll
    for (int o = 16; o; o >>= 1) m = fmaxf(m, __shfl_xor_sync(0xffffffffu, m, o));
    __shared__ float red[8];
    int w = tid >> 5, l = tid & 31;
    if (l == 0) red[w] = m;
    __syncthreads();
    if (tid == 0) {
        float t = red[0];
        for (int u = 1; u < 8; u++) t = fmaxf(t, red[u]);
        atomicMax(mode == 0 ? &g_max0 : &g_max1, __float_as_uint(t));
    }
}

__global__ __launch_bounds__(256) void zinit_kernel() {
    int bh = blockIdx.x >> 8, i = blockIdx.x & 255, j = threadIdx.x;
    float inv = 1.f / (__uint_as_float(g_max0) * __uint_as_float(g_max1));
    g_za[((size_t)bh * MM + i) * MM + j] = g_a2[((size_t)bh * MM + j) * MM + i] * inv;
}

// ---------- bf16 packed GEMMs (R13-proven) ----------
__global__ __launch_bounds__(256) void qkv_mma() {
    __shared__ u32 SA[2][128*20];
    __shared__ u32 SB[2][16*136];
    int tid = threadIdx.x;
    int row0 = blockIdx.x * 128, col0 = blockIdx.y * 128;
    int lane = tid & 31, wid = tid >> 5;
    int g = lane >> 2, t = lane & 3;
    int wm = (wid & 1) * 64, wn = (wid >> 1) * 32;
    int mi = lane >> 3;
    int lrow = (lane & 7) + (mi & 1) * 8;
    int lcol = (mi >> 1) * 4;
    float acc[4][4][4];
    #pragma unroll
    for (int i = 0; i < 4; i++) for (int j = 0; j < 4; j++) for (int u = 0; u < 4; u++) acc[i][j][u] = 0.f;
    uint4 ua[2], ub[2];
    auto LOAD = [&](int kt) {
        int kp0 = kt >> 1;
        #pragma unroll
        for (int p = 0; p < 2; p++) {
            int idx = tid + p * 256; int m = idx >> 2, kg = idx & 3;
            ua[p] = *(const uint4*)&g_xnh[(size_t)(row0 + m) * 256 + kp0 + kg * 4];
        }
        #pragma unroll
        for (int p = 0; p < 2; p++) {
            int idx = tid + p * 256; int kp = idx >> 5, n4 = (idx & 31) * 4;
            ub[p] = *(const uint4*)&g_wqkvh[(size_t)(kp0 + kp) * 384 + col0 + n4];
        }
    };
    auto STS = [&](int buf) {
        #pragma unroll
        for (int p = 0; p < 2; p++) {
            int idx = tid + p * 256; int m = idx >> 2, kg = idx & 3;
            *(uint4*)&SA[buf][m * 20 + kg * 4] = ua[p];
        }
        #pragma unroll
        for (int p = 0; p < 2; p++) {
            int idx = tid + p * 256; int kp = idx >> 5, n4 = (idx & 31) * 4;
            *(uint4*)&SB[buf][kp * 136 + n4] = ub[p];
        }
    };
    auto COMP = [&](int buf) {
        u32 sa0 = shaddr(&SA[buf][(wm + lrow) * 20 + lcol]);
        #pragma unroll
        for (int s = 0; s < 2; s++) {
            int kp = 8 * s + t;
            u32 af[4][4], bf[4][2];
            #pragma unroll
            for (int i = 0; i < 4; i++)
                ldsm4(af[i], sa0 + ((16 * i * 20 + 8 * s) << 2));
            #pragma unroll
            for (int j = 0; j < 4; j++) {
                int n = wn + 8 * j + g;
                bf[j][0] = SB[buf][kp * 136 + n];
                bf[j][1] = SB[buf][(kp + 4) * 136 + n];
            }
            #pragma unroll
            for (int i = 0; i < 4; i++)
                #pragma unroll
                for (int j = 0; j < 4; j++) mmab(acc[i][j], af[i], bf[j]);
        }
    };
    LOAD(0); STS(0); __syncthreads();
    for (int it = 0; it < 16; it++) {
        if (it + 1 < 16) LOAD((it + 1) * 32);
        COMP(it & 1);
        if (it + 1 < 16) { STS((it + 1) & 1); __syncthreads(); }
    }
    auto STORE2 = [&](int tok, int c, float v0, float v1) {
        int bb = tok >> 13, n = tok & 8191;
        int which = c >> 7, hd = c & 127, h = hd >> 6, d = hd & 63;
        size_t dst = (((size_t)(bb * HH + h)) * NSEQ + n) * 32 + (d >> 1);
        if (which == 0)      g_qh[dst] = pk2(v0 * 0.125f, v1 * 0.125f);
        else if (which == 1) g_kh[dst] = pk2(v0, v1);
        else                 g_vh[dst] = pk2(v0, v1);
    };
    #pragma unroll
    for (int i = 0; i < 4; i++) {
        int row = row0 + wm + 16 * i + g;
        #pragma unroll
        for (int j = 0; j < 4; j++) {
            int col = col0 + wn + 8 * j + 2 * t;
            STORE2(row, col, acc[i][j][0], acc[i][j][1]);
            STORE2(row + 8, col, acc[i][j][2], acc[i][j][3]);
        }
    }
}

__global__ __launch_bounds__(256) void outgemm_mma(const float* __restrict__ x,
                                                   const float* __restrict__ bout,
                                                   float* __restrict__ out) {
    __shared__ u32 SA[2][128*20];
    __shared__ u32 SB[2][16*136];
    int tid = threadIdx.x;
    int row0 = blockIdx.x * 128, col0 = blockIdx.y * 128;
    int lane = tid & 31, wid = tid >> 5;
    int g = lane >> 2, t = lane & 3;
    int wm = (wid & 1) * 64, wn = (wid >> 1) * 32;
    int mi = lane >> 3;
    int lrow = (lane & 7) + (mi & 1) * 8;
    int lcol = (mi >> 1) * 4;
    float acc[4][4][4];
    #pragma unroll
    for (int i = 0; i < 4; i++) for (int j = 0; j < 4; j++) for (int u = 0; u < 4; u++) acc[i][j][u] = 0.f;
    uint4 ua[2], ub[2];
    auto LOAD = [&](int kt) {
        int kp0 = kt >> 1;
        #pragma unroll
        for (int p = 0; p < 2; p++) {
            int idx = tid + p * 256; int m = idx >> 2, kg = idx & 3;
            int tok = row0 + m; int bb = tok >> 13, n = tok & 8191;
            int kp = kp0 + kg * 4;
            int h = kp >> 5, dp = kp & 31;
            ua[p] = *(const uint4*)&g_out1h[(((size_t)(bb * HH + h)) * NSEQ + n) * 32 + dp];
        }
        #pragma unroll
        for (int p = 0; p < 2; p++) {
            int idx = tid + p * 256; int kp = idx >> 5, n4 = (idx & 31) * 4;
            ub[p] = *(const uint4*)&g_wouth[(size_t)(kp0 + kp) * 512 + col0 + n4];
        }
    };
    auto STS = [&](int buf) {
        #pragma unroll
        for (int p = 0; p < 2; p++) {
            int idx = tid + p * 256; int m = idx >> 2, kg = idx & 3;
            *(uint4*)&SA[buf][m * 20 + kg * 4] = ua[p];
        }
        #pragma unroll
        for (int p = 0; p < 2; p++) {
            int idx = tid + p * 256; int kp = idx >> 5, n4 = (idx & 31) * 4;
            *(uint4*)&SB[buf][kp * 136 + n4] = ub[p];
        }
    };
    auto COMP = [&](int buf) {
        u32 sa0 = shaddr(&SA[buf][(wm + lrow) * 20 + lcol]);
        #pragma unroll
        for (int s = 0; s < 2; s++) {
            int kp = 8 * s + t;
            u32 af[4][4], bf[4][2];
            #pragma unroll
            for (int i = 0; i < 4; i++)
                ldsm4(af[i], sa0 + ((16 * i * 20 + 8 * s) << 2));
            #pragma unroll
            for (int j = 0; j < 4; j++) {
                int n = wn + 8 * j + g;
                bf[j][0] = SB[buf][kp * 136 + n];
                bf[j][1] = SB[buf][(kp + 4) * 136 + n];
            }
            #pragma unroll
            for (int i = 0; i < 4; i++)
                #pragma unroll
                for (int j = 0; j < 4; j++) mmab(acc[i][j], af[i], bf[j]);
        }
    };
    LOAD(0); STS(0); __syncthreads();
    for (int it = 0; it < 4; it++) {
        if (it + 1 < 4) LOAD((it + 1) * 32);
        COMP(it & 1);
        if (it + 1 < 4) { STS((it + 1) & 1); __syncthreads(); }
    }
    #pragma unroll
    for (int i = 0; i < 4; i++) {
        int row = row0 + wm + 16 * i + g;
        #pragma unroll
        for (int j = 0; j < 4; j++) {
            int col = col0 + wn + 8 * j + 2 * t;
            float2 bb = *(const float2*)&bout[col];
            float2 x0 = *(const float2*)&x[(size_t)row*DD + col];
            float2 x1 = *(const float2*)&x[(size_t)(row+8)*DD + col];
            *(float2*)&out[(size_t)row*DD + col] =
                make_float2(acc[i][j][0] + bb.x + x0.x, acc[i][j][1] + bb.y + x0.y);
            *(float2*)&out[(size_t)(row+8)*DD + col] =
                make_float2(acc[i][j][2] + bb.x + x1.x, acc[i][j][3] + bb.y + x1.y);
        }
    }
}

// pinv bmm (R11-proven, 24 launches)
__global__ __launch_bounds__(256) void bmm_mma(const float* __restrict__ A,
                                               const float* __restrict__ Bm,
                                               float* __restrict__ C,
                                               float alpha, float beta, float gam) {
    __shared__ u32 SA[2][64*20];
    __shared__ u32 SB[2][16*72];
    int bh = blockIdx.z;
    size_t base = (size_t)bh * MM * MM;
    int i0 = blockIdx.x * 64, j0 = blockIdx.y * 64;
    int tid = threadIdx.x;
    int lane = tid & 31, wid = tid >> 5;
    int g = lane >> 2, t = lane & 3;
    int wm = (wid & 3) * 16, wn = (wid >> 2) * 32;
    int mi = lane >> 3;
    int lrow = (lane & 7) + (mi & 1) * 8;
    int lcol = (mi >> 1) * 4;
    float acc[4][4];
    #pragma unroll
    for (int j = 0; j < 4; j++) for (int u = 0; u < 4; u++) acc[j][u] = 0.f;
    int am = tid >> 2, akg = tid & 3;
    int bkp = tid >> 4, bn4 = (tid & 15) * 4;
    float4 a1, a2, b1, b2;
    auto LOAD = [&](int kt) {
        const float* src = &A[base + (size_t)(i0 + am) * MM + kt + akg * 8];
        a1 = *(const float4*)src;
        a2 = *(const float4*)(src + 4);
        int k = kt + bkp * 2;
        b1 = *(const float4*)&Bm[base + (size_t)k * MM + j0 + bn4];
        b2 = *(const float4*)&Bm[base + (size_t)(k + 1) * MM + j0 + bn4];
    };
    auto STS = [&](int buf) {
        *(uint4*)&SA[buf][am * 20 + akg * 4] = pkA(a1, a2);
        *(uint4*)&SB[buf][bkp * 72 + bn4] = pkB(b1, b2);
    };
    auto COMP = [&](int buf) {
        u32 sa0 = shaddr(&SA[buf][(wm + lrow) * 20 + lcol]);
        #pragma unroll
        for (int s = 0; s < 2; s++) {
            int kp = 8 * s + t;
            u32 af[4], bf[4][2];
            ldsm4(af, sa0 + ((8 * s) << 2));
            #pragma unroll
            for (int j = 0; j < 4; j++) {
                int n = wn + 8 * j + g;
                bf[j][0] = SB[buf][kp * 72 + n];
                bf[j][1] = SB[buf][(kp + 4) * 72 + n];
            }
            #pragma unroll
            for (int j = 0; j < 4; j++) mmab(acc[j], af, bf[j]);
        }
    };
    LOAD(0); STS(0); __syncthreads();
    for (int it = 0; it < 8; it++) {
        if (it + 1 < 8) LOAD((it + 1) * 32);
        COMP(it & 1);
        if (it + 1 < 8) { STS((it + 1) & 1); __syncthreads(); }
    }
    #pragma unroll
    for (int j = 0; j < 4; j++) {
        #pragma unroll
        for (int u = 0; u < 4; u++) {
            int row = i0 + wm + g + (u >> 1) * 8;
            int col = j0 + wn + 8 * j + 2 * t + (u & 1);
            float r = alpha * acc[j][u];
            if (beta != 0.f) r += beta * A[base + (size_t)row * MM + col];
            if (row == col) r += gam;
            C[base + (size_t)row * MM + col] = r;
        }
    }
}

// NN, N=64 tf32 (W2 = Z @ a3v only)
__global__ __launch_bounds__(128) void nn64_mma(const float* __restrict__ A,
                                                const float* __restrict__ B,
                                                float* __restrict__ C,
                                                int lda, size_t aBatch, size_t bBatch,
                                                size_t cBatch, int kchunk) {
    __shared__ unsigned As[64*36];
    __shared__ unsigned Bs[32*72];
    int bh = blockIdx.z;
    int m0 = blockIdx.x * 64;
    const float* Ab = A + (size_t)bh * aBatch + (size_t)m0 * lda;
    const float* Bb = B + (size_t)bh * bBatch;
    int tid = threadIdx.x;
    int lane = tid & 31, wid = tid >> 5;
    int g = lane >> 2, t = lane & 3;
    int wm = (wid & 1) * 32, wn = (wid >> 1) * 32;
    float acc[2][4][4];
    #pragma unroll
    for (int i = 0; i < 2; i++) for (int j = 0; j < 4; j++) for (int u = 0; u < 4; u++) acc[i][j][u] = 0.f;
    int iters = kchunk / 32;
    for (int it = 0; it < iters; it++) {
        #pragma unroll
        for (int p = 0; p < 4; p++) {
            int idx = tid + p * 128; int m = idx >> 3, c = (idx & 7) * 4;
            float4 v = *(const float4*)&Ab[(size_t)m * lda + it*32 + c];
            *(uint4*)&As[m*36+c] = make_uint4(f2tf(v.x), f2tf(v.y), f2tf(v.z), f2tf(v.w));
        }
        #pragma unroll
        for (int p = 0; p < 4; p++) {
            int idx = tid + p * 128; int k = idx >> 4, c = (idx & 15) * 4;
            float4 v = *(const float4*)&Bb[(size_t)(it*32 + k) * 64 + c];
            *(uint4*)&Bs[k*72+c] = make_uint4(f2tf(v.x), f2tf(v.y), f2tf(v.z), f2tf(v.w));
        }
        __syncthreads();
        #pragma unroll
        for (int s = 0; s < 4; s++) {
            unsigned af[2][4], bf[4][2];
            #pragma unroll
            for (int i = 0; i < 2; i++) {
                const unsigned* p = &As[(wm + 16*i + g)*36 + 8*s + t];
                af[i][0] = p[0]; af[i][1] = p[288]; af[i][2] = p[4]; af[i][3] = p[292];
            }
            #pragma unroll
            for (int j = 0; j < 4; j++) {
                const unsigned* p = &Bs[(8*s + t)*72 + wn + 8*j + g];
                bf[j][0] = p[0]; bf[j][1] = p[288];
            }
            #pragma unroll
            for (int i = 0; i < 2; i++)
                #pragma unroll
                for (int j = 0; j < 4; j++) mma8(acc[i][j], af[i], bf[j]);
        }
        __syncthreads();
    }
    float* Cb = C + (size_t)bh * cBatch + (size_t)m0 * 64;
    #pragma unroll
    for (int i = 0; i < 2; i++) {
        int row = wm + 16*i + g;
        #pragma unroll
        for (int j = 0; j < 4; j++) {
            int col = wn + 8*j + 2*t;
            Cb[(size_t)row*64 + col]       = acc[i][j][0];
            Cb[(size_t)row*64 + col+1]     = acc[i][j][1];
            Cb[(size_t)(row+8)*64 + col]   = acc[i][j][2];
            Cb[(size_t)(row+8)*64 + col+1] = acc[i][j][3];
        }
    }
}

// ---------- fused flash kernels (R15-proven) ----------
__global__ __launch_bounds__(256) void attn3_kernel() {
    extern __shared__ u32 smu[];
    u32* QS = smu;
    u32* KS = QS + 64*36;
    u32* VS = KS + 128*36;
    float* SS = (float*)(VS + 64*72);
    u32* PS = (u32*)(SS + 64*132);
    float* sm_m = (float*)(PS + 64*68);
    float* sm_l = sm_m + 64;
    float* sm_sc = sm_l + 64;
    int tid = threadIdx.x;
    int r0 = blockIdx.x * 64, sp = blockIdx.y, bh = blockIdx.z;
    int lane = tid & 31, wid = tid >> 5;
    int g = lane >> 2, t = lane & 3;
    int mi = lane >> 3;
    int lrow = (lane & 7) + (mi & 1) * 8;
    int lcol = (mi >> 1) * 4;
    #pragma unroll
    for (int p = 0; p < 2; p++) {
        int idx = tid + p * 256; int m = idx >> 3, kg = idx & 7;
        const float* src = &g_ql[((size_t)bh * MM + r0 + m) * DH + kg * 8];
        *(uint4*)&QS[m*36 + kg*4] = pkA(*(const float4*)src, *(const float4*)(src + 4));
    }
    if (tid < 64) { sm_m[tid] = -1e30f; sm_l[tid] = 0.f; }
    int m0 = (wid & 3) * 16;
    int n0s = (wid >> 2) * 64;
    int n0o = (wid >> 2) * 32;
    float acco[4][4];
    #pragma unroll
    for (int j = 0; j < 4; j++) for (int u = 0; u < 4; u++) acco[j][u] = 0.f;
    __syncthreads();
    for (int ch = 0; ch < 8; ch++) {
        int k0 = sp * 1024 + ch * 128;
        #pragma unroll
        for (int p = 0; p < 4; p++) {
            int idx = tid + p * 256; int key = idx >> 3, kg = idx & 7;
            *(uint4*)&KS[key*36 + kg*4] =
                *(const uint4*)&g_kh[((size_t)bh * NSEQ + k0 + key) * 32 + kg * 4];
        }
        #pragma unroll
        for (int p = 0; p < 4; p++) {
            int idx = tid + p * 256; int kp = idx >> 4, n4 = (idx & 15) * 4;
            uint2 va = *(const uint2*)&g_vh[((size_t)bh * NSEQ + k0 + 2*kp) * 32 + (idx & 15) * 2];
            uint2 vb = *(const uint2*)&g_vh[((size_t)bh * NSEQ + k0 + 2*kp + 1) * 32 + (idx & 15) * 2];
            VS[kp*72 + n4 + 0] = (va.x & 0xFFFFu) | (vb.x << 16);
            VS[kp*72 + n4 + 1] = (va.x >> 16) | (vb.x & 0xFFFF0000u);
            VS[kp*72 + n4 + 2] = (va.y & 0xFFFFu) | (vb.y << 16);
            VS[kp*72 + n4 + 3] = (va.y >> 16) | (vb.y & 0xFFFF0000u);
        }
        __syncthreads();
        float accs[8][4];
        #pragma unroll
        for (int j = 0; j < 8; j++) for (int u = 0; u < 4; u++) accs[j][u] = 0.f;
        u32 qa = shaddr(&QS[(m0 + lrow)*36 + lcol]);
        u32 ka = shaddr(&KS[(n0s + lrow)*36 + lcol]);
        #pragma unroll
        for (int s = 0; s < 4; s++) {
            u32 af[4];
            ldsm4(af, qa + ((8 * s) << 2));
            #pragma unroll
            for (int jj = 0; jj < 4; jj++) {
                u32 bfr[4];
                ldsm4(bfr, ka + ((16*jj*36 + 8*s) << 2));
                u32 b0[2] = {bfr[0], bfr[2]};
                u32 b1[2] = {bfr[1], bfr[3]};
                mmab(accs[2*jj], af, b0);
                mmab(accs[2*jj+1], af, b1);
            }
        }
        #pragma unroll
        for (int j = 0; j < 8; j++) {
            int col = n0s + 8*j + 2*t;
            *(float2*)&SS[(m0+g)*132 + col]   = make_float2(accs[j][0], accs[j][1]);
            *(float2*)&SS[(m0+g+8)*132 + col] = make_float2(accs[j][2], accs[j][3]);
        }
        __syncthreads();
        {
            int row = tid >> 2, t2 = tid & 3;
            float* Sr = &SS[row*132 + t2*32];
            float cmax = -1e30f;
            #pragma unroll
            for (int c = 0; c < 32; c++) cmax = fmaxf(cmax, Sr[c]);
            cmax = fmaxf(cmax, __shfl_xor_sync(0xffffffffu, cmax, 1));
            cmax = fmaxf(cmax, __shfl_xor_sync(0xffffffffu, cmax, 2));
            float mold = sm_m[row];
            float mnew = fmaxf(mold, cmax);
            float csum = 0.f;
            #pragma unroll
            for (int c = 0; c < 32; c += 2) {
                float pv0 = __expf(Sr[c] - mnew);
                float pv1 = __expf(Sr[c+1] - mnew);
                csum += pv0 + pv1;
                PS[row*68 + t2*16 + (c >> 1)] = pk2(pv0, pv1);
            }
            csum += __shfl_xor_sync(0xffffffffu, csum, 1);
            csum += __shfl_xor_sync(0xffffffffu, csum, 2);
            if (t2 == 0) {
                float scv = __expf(mold - mnew);
                sm_sc[row] = scv;
                sm_l[row] = sm_l[row] * scv + csum;
                sm_m[row] = mnew;
            }
        }
        __syncthreads();
        {
            float s0 = sm_sc[m0 + g], s1 = sm_sc[m0 + g + 8];
            #pragma unroll
            for (int j = 0; j < 4; j++) {
                acco[j][0] *= s0; acco[j][1] *= s0;
                acco[j][2] *= s1; acco[j][3] *= s1;
            }
            u32 pa = shaddr(&PS[(m0 + lrow)*68 + lcol]);
            #pragma unroll
            for (int s = 0; s < 8; s++) {
                u32 af[4];
                ldsm4(af, pa + ((8 * s) << 2));
                #pragma unroll
                for (int j = 0; j < 4; j++) {
                    int n = n0o + 8*j + g;
                    u32 bf2[2];
                    bf2[0] = VS[(8*s + t)*72 + n];
                    bf2[1] = VS[(8*s + t + 4)*72 + n];
                    mmab(acco[j], af, bf2);
                }
            }
        }
        __syncthreads();
    }
    size_t pb = ((size_t)(bh*NSP + sp) * MM + r0);
    #pragma unroll
    for (int j = 0; j < 4; j++) {
        int col = n0o + 8*j + 2*t;
        *(float2*)&g_part[(pb + m0 + g) * DH + col]     = make_float2(acco[j][0], acco[j][1]);
        *(float2*)&g_part[(pb + m0 + g + 8) * DH + col] = make_float2(acco[j][2], acco[j][3]);
    }
    if (tid < 64) {
        g_m[(bh*NSP + sp) * MM + r0 + tid] = sm_m[tid];
        g_l[(bh*NSP + sp) * MM + r0 + tid] = sm_l[tid];
    }
}

__global__ void attn_combine() {
    int idx = blockIdx.x * 256 + threadIdx.x;
    int bh = idx >> 14, rem = idx & 16383, row = rem >> 6, d = rem & 63;
    float ms = -1e30f;
    #pragma unroll
    for (int s = 0; s < NSP; s++) ms = fmaxf(ms, g_m[(bh*NSP+s)*MM + row]);
    float num = 0.f, den = 0.f;
    #pragma unroll
    for (int s = 0; s < NSP; s++) {
        float e = __expf(g_m[(bh*NSP+s)*MM + row] - ms);
        num += g_part[((size_t)(bh*NSP+s)*MM + row)*DH + d] * e;
        den += g_l[(bh*NSP+s)*MM + row] * e;
    }
    g_a3v[((size_t)bh*MM + row)*DH + d] = num / den;
}

// attn1 (R13/R15-proven, 256 threads)
__global__ __launch_bounds__(256) void attn1_kernel(const float* __restrict__ wres) {
    extern __shared__ u32 smu[];
    u32* QS  = smu;
    u32* KLS = QS + 64*36;
    u32* W2S = KLS + 256*36;
    float* SS = (float*)(W2S + 128*72);
    u32* PS = (u32*)(SS + 64*264);
    float* CONV = (float*)(PS + 64*132);
    float* sm_l = CONV + 64*66;
    float* wl = sm_l + 64;
    float* VC = SS;
    int tid = threadIdx.x;
    int r0 = blockIdx.x * 64, bh = blockIdx.y;
    int lane = tid & 31, wid = tid >> 5;
    int g = lane >> 2, t = lane & 3;
    int mi = lane >> 3;
    int lrow = (lane & 7) + (mi & 1) * 8;
    int lcol = (mi >> 1) * 4;
    if (tid < KERN) wl[tid] = wres[(bh & 1) * KERN + tid];
    #pragma unroll
    for (int p = 0; p < 2; p++) {
        int idx = tid + p * 256; int m = idx >> 3, kg = idx & 7;
        *(uint4*)&QS[m*36 + kg*4] =
            *(const uint4*)&g_qh[((size_t)bh * NSEQ + r0 + m) * 32 + kg * 4];
    }
    #pragma unroll
    for (int p = 0; p < 8; p++) {
        int idx = tid + p * 256; int m = idx >> 3, kg = idx & 7;
        const float* src = &g_kl[((size_t)bh * MM + m) * DH + kg * 8];
        *(uint4*)&KLS[m*36 + kg*4] = pkA(*(const float4*)src, *(const float4*)(src + 4));
    }
    #pragma unroll
    for (int p = 0; p < 8; p++) {
        int idx = tid + p * 256; int kp = idx >> 4, n4 = (idx & 15) * 4;
        const float* s0 = &g_w2[((size_t)bh * MM + 2*kp) * DH + n4];
        *(uint4*)&W2S[kp*72 + n4] = pkB(*(const float4*)s0, *(const float4*)(s0 + DH));
    }
    #pragma unroll
    for (int p = 0; p < 6; p++) {
        int idx = tid + p * 256; int li = idx >> 4, d4 = (idx & 15) * 4;
        int n = r0 - 16 + li;
        float4 val = make_float4(0.f, 0.f, 0.f, 0.f);
        if (n >= 0 && n < NSEQ) {
            uint2 v2 = *(const uint2*)&g_vh[((size_t)bh * NSEQ + n) * 32 + (idx & 15) * 2];
            val = make_float4(blo(v2.x), bhi(v2.x), blo(v2.y), bhi(v2.y));
        }
        *(float4*)&VC[li * 68 + d4] = val;
    }
    __syncthreads();
    {
        int rr = tid >> 2, ds = (tid & 3) * 16;
        #pragma unroll
        for (int d4 = 0; d4 < 4; d4++) {
            float4 a4 = make_float4(0.f, 0.f, 0.f, 0.f);
            #pragma unroll
            for (int tap = 0; tap < KERN; tap++) {
                float w = wl[tap];
                float4 vv = *(const float4*)&VC[(rr + tap) * 68 + ds + d4 * 4];
                a4.x += w * vv.x; a4.y += w * vv.y; a4.z += w * vv.z; a4.w += w * vv.w;
            }
            CONV[rr * 66 + ds + d4 * 4 + 0] = a4.x;
            CONV[rr * 66 + ds + d4 * 4 + 1] = a4.y;
            CONV[rr * 66 + ds + d4 * 4 + 2] = a4.z;
            CONV[rr * 66 + ds + d4 * 4 + 3] = a4.w;
        }
    }
    int m0 = (wid & 3) * 16;
    int n0s = (wid >> 2) * 128;
    float accs[16][4];
    #pragma unroll
    for (int j = 0; j < 16; j++) for (int u = 0; u < 4; u++) accs[j][u] = 0.f;
    u32 qa = shaddr(&QS[(m0 + lrow)*36 + lcol]);
    u32 ka = shaddr(&KLS[(n0s + lrow)*36 + lcol]);
    #pragma unroll
    for (int s = 0; s < 4; s++) {
        u32 af[4];
        ldsm4(af, qa + ((8 * s) << 2));
        #pragma unroll
        for (int jj = 0; jj < 8; jj++) {
            u32 bfr[4];
            ldsm4(bfr, ka + ((16*jj*36 + 8*s) << 2));
            u32 b0[2] = {bfr[0], bfr[2]};
            u32 b1[2] = {bfr[1], bfr[3]};
            mmab(accs[2*jj], af, b0);
            mmab(accs[2*jj+1], af, b1);
        }
    }
    __syncthreads();
    #pragma unroll
    for (int j = 0; j < 16; j++) {
        int col = n0s + 8*j + 2*t;
        *(float2*)&SS[(m0+g)*264 + col]   = make_float2(accs[j][0], accs[j][1]);
        *(float2*)&SS[(m0+g+8)*264 + col] = make_float2(accs[j][2], accs[j][3]);
    }
    __syncthreads();
    {
        int row = tid >> 2, t2 = tid & 3;
        float* Sr = &SS[row*264 + t2*64];
        float cmax = -1e30f;
        #pragma unroll
        for (int c = 0; c < 64; c++) cmax = fmaxf(cmax, Sr[c]);
        cmax = fmaxf(cmax, __shfl_xor_sync(0xffffffffu, cmax, 1));
        cmax = fmaxf(cmax, __shfl_xor_sync(0xffffffffu, cmax, 2));
        float csum = 0.f;
        #pragma unroll
        for (int c = 0; c < 64; c += 2) {
            float pv0 = __expf(Sr[c] - cmax);
            float pv1 = __expf(Sr[c+1] - cmax);
            csum += pv0 + pv1;
            PS[row*132 + t2*32 + (c >> 1)] = pk2(pv0, pv1);
        }
        csum += __shfl_xor_sync(0xffffffffu, csum, 1);
        csum += __shfl_xor_sync(0xffffffffu, csum, 2);
        if (t2 == 0) sm_l[row] = csum;
    }
    __syncthreads();
    int n0o = (wid >> 2) * 32;
    float acco[4][4];
    #pragma unroll
    for (int j = 0; j < 4; j++) for (int u = 0; u < 4; u++) acco[j][u] = 0.f;
    u32 pa = shaddr(&PS[(m0 + lrow)*132 + lcol]);
    #pragma unroll
    for (int s = 0; s < 16; s++) {
        u32 af[4];
        ldsm4(af, pa + ((8 * s) << 2));
        #pragma unroll
        for (int j = 0; j < 4; j++) {
            int n = n0o + 8*j + g;
            u32 bf2[2];
            bf2[0] = W2S[(8*s + t)*72 + n];
            bf2[1] = W2S[(8*s + t + 4)*72 + n];
            mmab(acco[j], af, bf2);
        }
    }
    float il0 = 1.f / sm_l[m0 + g], il1 = 1.f / sm_l[m0 + g + 8];
    size_t ob = (size_t)bh * NSEQ + r0;
    int row0l = m0 + g, row1l = m0 + g + 8;
    #pragma unroll
    for (int j = 0; j < 4; j++) {
        int col = n0o + 8*j + 2*t;
        int dp = col >> 1;
        float v00 = acco[j][0]*il0 + CONV[row0l*66 + col];
        float v01 = acco[j][1]*il0 + CONV[row0l*66 + col + 1];
        float v10 = acco[j][2]*il1 + CONV[row1l*66 + col];
        float v11 = acco[j][3]*il1 + CONV[row1l*66 + col + 1];
        g_out1h[(ob + row0l) * 32 + dp] = pk2(v00, v01);
        g_out1h[(ob + row1l) * 32 + dp] = pk2(v10, v11);
    }
}

// ---------------- launch ----------------
extern "C" void kernel_launch(void* const* d_in, const int* in_sizes, int n_in,
                              void* d_out, int out_size) {
    const float* x     = (const float*)d_in[0];
    const float* gamma = (const float*)d_in[1];
    const float* beta  = (const float*)d_in[2];
    const float* wqkv  = (const float*)d_in[3];
    const float* wout  = (const float*)d_in[4];
    const float* bout  = (const float*)d_in[5];
    const float* wres  = (const float*)d_in[6];
    float* out = (float*)d_out;

    float *pA2, *pXZ, *pT1, *pT2, *pZA, *pZB, *pA3V, *pW2;
    cudaGetSymbolAddress((void**)&pA2, g_a2);
    cudaGetSymbolAddress((void**)&pXZ, g_xz);
    cudaGetSymbolAddress((void**)&pT1, g_t1);
    cudaGetSymbolAddress((void**)&pT2, g_t2);
    cudaGetSymbolAddress((void**)&pZA, g_za);
    cudaGetSymbolAddress((void**)&pZB, g_zb);
    cudaGetSymbolAddress((void**)&pA3V, g_a3v);
    cudaGetSymbolAddress((void**)&pW2, g_w2);

    cudaFuncSetAttribute(attn3_kernel, cudaFuncAttributeMaxDynamicSharedMemorySize, 98048);
    cudaFuncSetAttribute(attn1_kernel, cudaFuncAttributeMaxDynamicSharedMemorySize, 201664);

    init_kernel<<<1, 1>>>();
    prepack_kernel<<<512, 256>>>(wqkv, wout);
    ln_kernel<<<TOK, 128>>>(x, gamma, beta);
    qkv_mma<<<dim3(TOK / 128, 3), 256>>>();
    landmark_kernel<<<dim3(BH, MM / 4), 256>>>();
    sim2_kernel<<<BH * MM, 256>>>();
    absmax_kernel<<<dim3(BH, 2), 256>>>();
    zinit_kernel<<<BH * MM, 256>>>();

    float* zc = pZA;
    float* zn = pZB;
    for (int it = 0; it < 6; it++) {
        bmm_mma<<<dim3(4, 4, BH), 256>>>(pA2, zc, pXZ, 1.f, 0.f, 0.f);
        bmm_mma<<<dim3(4, 4, BH), 256>>>(pXZ, pXZ, pT1, 1.f, -7.f, 15.f);
        bmm_mma<<<dim3(4, 4, BH), 256>>>(pXZ, pT1, pT2, -1.f, 0.f, 13.f);
        bmm_mma<<<dim3(4, 4, BH), 256>>>(zc, pT2, zn, 0.25f, 0.f, 0.f);
        float* t = zc; zc = zn; zn = t;
    }

    attn3_kernel<<<dim3(4, NSP, BH), 256, 98048>>>();
    attn_combine<<<512, 256>>>();
    nn64_mma<<<dim3(4, 1, BH), 128>>>(zc, pA3V, pW2, MM,
        (size_t)MM * MM, (size_t)MM * 64, (size_t)MM * 64, MM);
    attn1_kernel<<<dim3(NSEQ / 64, BH), 256, 201664>>>(wres);
    outgemm_mma<<<dim3(TOK / 128, 4), 256>>>(x, bout, out);
}